// round 11
// baseline (speedup 1.0000x reference)
#include <cuda_runtime.h>
#include <math.h>

#define NB 8192
#define TT 21

// ---------------- scratch (static device allocations; no cudaMalloc) -------
__device__ float d_TW[5056 * 192];      // token-part of layer0 x@Wx (+bias), per dir
__device__ float d_HW[2 * 96];          // hole row x@Wx (+bias), per dir
__device__ float d_XW0[2 * TT * NB * 96];
__device__ unsigned d_maskFlags;        // dtype-detection flags for mask buffers

// ---------------- f32x2 helpers --------------------------------------------
typedef unsigned long long u64t;
__device__ __forceinline__ u64t pack2(float lo, float hi) {
    u64t r; asm("mov.b64 %0,{%1,%2};" : "=l"(r) : "f"(lo), "f"(hi)); return r;
}
__device__ __forceinline__ void unpack2(u64t v, float& lo, float& hi) {
    asm("mov.b64 {%0,%1},%2;" : "=f"(lo), "=f"(hi) : "l"(v));
}
__device__ __forceinline__ u64t fma2(u64t a, u64t b, u64t c) {
    u64t d; asm("fma.rn.f32x2 %0,%1,%2,%3;" : "=l"(d) : "l"(a), "l"(b), "l"(c)); return d;
}
__device__ __forceinline__ float sigf(float x)  { return 1.0f / (1.0f + __expf(-x)); }
__device__ __forceinline__ float tanhx(float x) { return 1.0f - 2.0f / (__expf(2.0f * x) + 1.0f); }

// ---------------- K0: mask dtype detection ---------------------------------
__global__ void k_reset() { d_maskFlags = 0u; }

__global__ void k_detect(const unsigned* __restrict__ m) {
    unsigned f = 0;
    for (int i = blockIdx.x * blockDim.x + threadIdx.x; i < 204800;
         i += gridDim.x * blockDim.x) {
        unsigned w = m[i];
        if (w != 0u && w != 1u) f |= 1u;
        if (w != 0u && w != 0x3F800000u) f |= 2u;
    }
    if (f) atomicOr(&d_maskFlags, f);
}

// ---------------- K1a: token table as tiled GEMM ---------------------------
// TW[v][d*96+c] = bias + sum_{k<128} tok_emb[v][k] * Wx[k][d*96+c]
// 79 blocks x 256 thr; tile M=64 vocab rows, N=192 cols, K=128 in 4 chunks.
__global__ void k_tables2(const float* __restrict__ tok_emb,
                          const float* __restrict__ gk_fw, const float* __restrict__ gb_fw,
                          const float* __restrict__ ck_fw, const float* __restrict__ cb_fw,
                          const float* __restrict__ gk_bw, const float* __restrict__ gb_bw,
                          const float* __restrict__ ck_bw, const float* __restrict__ cb_bw)
{
    __shared__ float sA[64][33];
    __shared__ float sW[32][192];
    __shared__ float sB[192];
    int b0 = blockIdx.x * 64;
    int tid = threadIdx.x, tx = tid & 15, ty = tid >> 4;

    if (tid < 192) {
        int d = tid / 96, c = tid % 96;
        sB[tid] = (c < 64) ? (d ? gb_bw : gb_fw)[c] : (d ? cb_bw : cb_fw)[c - 64];
    }
    __syncthreads();

    float acc[4][12];
    #pragma unroll
    for (int c = 0; c < 12; c++) {
        float bv = sB[tx + 16 * c];
        #pragma unroll
        for (int r = 0; r < 4; r++) acc[r][c] = bv;
    }

    for (int kc = 0; kc < 4; kc++) {
        for (int i = tid; i < 64 * 32; i += 256) {
            int row = i >> 5, kk = i & 31;
            int v = b0 + row;
            sA[row][kk] = (v < 5000) ? tok_emb[v * 128 + kc * 32 + kk] : 0.0f;
        }
        for (int i = tid; i < 32 * 192; i += 256) {
            int k = i / 192, c = i % 192, d = c / 96, cc = c % 96;
            const float* gkp = d ? gk_bw : gk_fw;
            const float* ckp = d ? ck_bw : ck_fw;
            int row = kc * 32 + k;
            sW[k][c] = (cc < 64) ? gkp[row * 64 + cc] : ckp[row * 32 + (cc - 64)];
        }
        __syncthreads();
        #pragma unroll
        for (int k = 0; k < 32; k++) {
            float a[4];
            #pragma unroll
            for (int r = 0; r < 4; r++) a[r] = sA[ty * 4 + r][k];
            #pragma unroll
            for (int c = 0; c < 12; c++) {
                float bv = sW[k][tx + 16 * c];
                #pragma unroll
                for (int r = 0; r < 4; r++) acc[r][c] = fmaf(a[r], bv, acc[r][c]);
            }
        }
        __syncthreads();
    }

    #pragma unroll
    for (int r = 0; r < 4; r++) {
        int v = b0 + ty * 4 + r;
        if (v < 5000)
            #pragma unroll
            for (int c = 0; c < 12; c++)
                d_TW[(size_t)v * 192 + tx + 16 * c] = acc[r][c];
    }
}

// ---------------- K1b: hole row (full 160-dim input) -----------------------
__global__ void k_hole(const float* __restrict__ hole,
                       const float* __restrict__ gk_fw, const float* __restrict__ gb_fw,
                       const float* __restrict__ ck_fw, const float* __restrict__ cb_fw,
                       const float* __restrict__ gk_bw, const float* __restrict__ gb_bw,
                       const float* __restrict__ ck_bw, const float* __restrict__ cb_bw)
{
    __shared__ float s[160];
    int tid = threadIdx.x;              // 192 threads
    if (tid < 160) s[tid] = hole[tid];
    __syncthreads();

    int dir = tid / 96, col = tid % 96;
    const float* gk = dir ? gk_bw : gk_fw;
    const float* ck = dir ? ck_bw : ck_fw;
    const float* gb = dir ? gb_bw : gb_fw;
    const float* cb = dir ? cb_bw : cb_fw;
    const float* w;
    int stride;
    float acc;
    if (col < 64) { w = gk + col;        stride = 64; acc = gb[col]; }
    else          { w = ck + (col - 64); stride = 32; acc = cb[col - 64]; }
    #pragma unroll 8
    for (int k = 0; k < 160; k++) acc = fmaf(s[k], w[k * stride], acc);
    d_HW[tid] = acc;
}

// ---------------- K2: layer0 x-precompute GEMM, typemax fused, both dirs ---
__global__ void k_xw0(const int* __restrict__ tok_b, const int* __restrict__ tok_a,
                      const int* __restrict__ typ_b, const void* __restrict__ msk_b,
                      const int* __restrict__ typ_a, const void* __restrict__ msk_a,
                      const float* __restrict__ yemb,
                      const float* __restrict__ gkx_fw, const float* __restrict__ ckx_fw,
                      const float* __restrict__ gkx_bw, const float* __restrict__ ckx_bw)
{
    __shared__ float sA[64][33];
    __shared__ float sW[32][96];
    __shared__ int   sTok[64];
    int rt  = blockIdx.x;                // 0..2687
    int t   = rt >> 7;
    int b0  = (rt & 127) << 6;
    int tid = threadIdx.x;
    int tx = tid & 15, ty = tid >> 4;

    if (t == 10) {                       // hole: identical row for all b
        for (int dir = 0; dir < 2; dir++) {
            float* outp = d_XW0 + ((size_t)(dir * TT + t) * NB + b0) * 96;
            #pragma unroll
            for (int c = 0; c < 6; c++) {
                int col = tx + 16 * c;
                float v = d_HW[dir * 96 + col];
                #pragma unroll
                for (int r = 0; r < 4; r++) outp[(ty * 4 + r) * 96 + col] = v;
            }
        }
        return;
    }

    // ---- fused masked type-max (computed ONCE, shared by both dirs) ----
    {
        unsigned flags = d_maskFlags;
        int mode = ((flags & 1u) == 0u) ? 1 : (((flags & 2u) == 0u) ? 2 : 0);
        int wid = tid >> 5, lane = tid & 31;
        int pos = (t < 10) ? t : t - 11;
        const int*  typ = (t < 10) ? typ_b : typ_a;
        const void* msk = (t < 10) ? msk_b : msk_a;
        for (int rr = wid; rr < 64; rr += 8) {
            int bb = b0 + rr;
            int base = (bb * 10 + pos) * 10;
            float m = -3.402823e38f;
            #pragma unroll
            for (int nt = 0; nt < 10; nt++) {
                int id = typ[base + nt];
                bool valid;
                if (mode == 1)      valid = ((const int*)msk)[base + nt] != 0;
                else if (mode == 2) valid = ((const float*)msk)[base + nt] != 0.0f;
                else                valid = ((const unsigned char*)msk)[base + nt] != 0;
                m = fmaxf(m, yemb[id * 32 + lane] + (valid ? 0.0f : -1000.0f));
            }
            sA[rr][lane] = m;
        }
    }
    if (tid < 64) {
        int bb = b0 + tid;
        sTok[tid] = (t < 10) ? tok_b[bb * 10 + t] : tok_a[bb * 10 + (t - 11)];
    }

    for (int dir = 0; dir < 2; dir++) {
        const float* gkx = dir ? gkx_bw : gkx_fw;
        const float* ckx = dir ? ckx_bw : ckx_fw;
        for (int i = tid; i < 32 * 64; i += 256) sW[i >> 6][i & 63]        = gkx[i];
        for (int i = tid; i < 32 * 32; i += 256) sW[i >> 5][64 + (i & 31)] = ckx[i];
        __syncthreads();

        float acc[4][6];
        #pragma unroll
        for (int r = 0; r < 4; r++)
            #pragma unroll
            for (int c = 0; c < 6; c++) acc[r][c] = 0.0f;

        #pragma unroll
        for (int k = 0; k < 32; k++) {
            float a[4], bv[6];
            #pragma unroll
            for (int r = 0; r < 4; r++) a[r] = sA[ty * 4 + r][k];
            #pragma unroll
            for (int c = 0; c < 6; c++) bv[c] = sW[k][tx + 16 * c];
            #pragma unroll
            for (int r = 0; r < 4; r++)
                #pragma unroll
                for (int c = 0; c < 6; c++) acc[r][c] = fmaf(a[r], bv[c], acc[r][c]);
        }

        float* outp = d_XW0 + ((size_t)(dir * TT + t) * NB + b0) * 96;
        #pragma unroll
        for (int r = 0; r < 4; r++) {
            const float* tw = d_TW + (size_t)sTok[ty * 4 + r] * 192 + dir * 96;
            #pragma unroll
            for (int c = 0; c < 6; c++) {
                int col = tx + 16 * c;
                outp[(ty * 4 + r) * 96 + col] = acc[r][c] + tw[col];
            }
        }
        __syncthreads();                 // before restaging sW for next dir
    }
}

// ---------------- K3: fused recurrence (layer0 -> xw1 GEMV -> layer1) ------
// 1024 threads = 32 warps; warp = (dir, row); 16 batch rows per block.
// smem (floats):
//  G0R/G0U/C0, G1R/G1U/C1: k-paired rec weights [dir][k2][lane][2]  6 x 2048
//  W1X: layer1 x-part [dir][64][96]                                 12288
//  B1:  layer1 bias [dir][96]                                       192
//  Y:   layer0 output, channel-major [16 rows][64 ch][22]           22528
//  H:   per-warp h/rh broadcast buffers [32][72]                    2304
#define SM_G0R 0
#define SM_G0U 2048
#define SM_C0  4096
#define SM_G1R 6144
#define SM_G1U 8192
#define SM_C1  10240
#define SM_W1X 12288
#define SM_B1  24576
#define SM_Y   24768
#define SM_H   47296
#define SM_TOTF 49600
#define SM_BYTES (SM_TOTF * 4)

__global__ __launch_bounds__(1024, 1)
void k_fused(const float* __restrict__ gk_fw0, const float* __restrict__ ck_fw0,
             const float* __restrict__ gk_bw0, const float* __restrict__ ck_bw0,
             const float* __restrict__ gk_fw1, const float* __restrict__ gb_fw1,
             const float* __restrict__ ck_fw1, const float* __restrict__ cb_fw1,
             const float* __restrict__ gk_bw1, const float* __restrict__ gb_bw1,
             const float* __restrict__ ck_bw1, const float* __restrict__ cb_bw1,
             float* __restrict__ out)
{
    extern __shared__ float sm[];
    int tid = threadIdx.x;

    // ---- stage all weights once (k-paired layouts for rec) ----
    for (int i = tid; i < 2048; i += 1024) {
        int p = i & 1, ln = (i >> 1) & 31, k2 = (i >> 6) & 15, d = i >> 10;
        const float* gk0 = d ? gk_bw0 : gk_fw0;
        const float* ck0 = d ? ck_bw0 : ck_fw0;
        const float* gk1 = d ? gk_bw1 : gk_fw1;
        const float* ck1 = d ? ck_bw1 : ck_fw1;
        int r0 = 160 + 2 * k2 + p;       // layer0 h-part rows
        int r1 = 64 + 2 * k2 + p;        // layer1 h-part rows
        sm[SM_G0R + i] = gk0[r0 * 64 + ln];
        sm[SM_G0U + i] = gk0[r0 * 64 + 32 + ln];
        sm[SM_C0  + i] = ck0[r0 * 32 + ln];
        sm[SM_G1R + i] = gk1[r1 * 64 + ln];
        sm[SM_G1U + i] = gk1[r1 * 64 + 32 + ln];
        sm[SM_C1  + i] = ck1[r1 * 32 + ln];
    }
    for (int i = tid; i < 12288; i += 1024) {
        int d = i / 6144, rem = i % 6144, k = rem / 96, c = rem % 96;
        const float* gk1 = d ? gk_bw1 : gk_fw1;
        const float* ck1 = d ? ck_bw1 : ck_fw1;
        sm[SM_W1X + i] = (c < 64) ? gk1[k * 64 + c] : ck1[k * 32 + (c - 64)];
    }
    if (tid < 192) {
        int d = tid / 96, c = tid % 96;
        sm[SM_B1 + tid] = (c < 64) ? (d ? gb_bw1 : gb_fw1)[c]
                                   : (d ? cb_bw1 : cb_fw1)[c - 64];
    }
    __syncthreads();

    int lane = tid & 31, wid = tid >> 5;
    int dir = wid >> 4, r = wid & 15;
    int b = blockIdx.x * 16 + r;
    float* yrow = sm + SM_Y + r * 1408;              // [64 ch][22]
    float* hbuf = sm + SM_H + wid * 72;              // h at +0, rh at +36
    const float* g0r = sm + SM_G0R + dir * 1024;
    const float* g0u = sm + SM_G0U + dir * 1024;
    const float* c0w = sm + SM_C0  + dir * 1024;

    // ---- layer0 recurrence; Y written channel-major into smem ----
    {
        float h = 0.0f;
        int t0 = dir ? 20 : 0;
        const float* xw = d_XW0 + ((size_t)(dir * TT + t0) * NB + b) * 96;
        float nr = xw[lane], nu = xw[32 + lane], nc = xw[64 + lane];
        for (int s = 0; s < 21; s++) {
            int t = dir ? 20 - s : s;
            float xr = nr, xu = nu, xc = nc;
            if (s < 20) {
                int t2 = dir ? t - 1 : t + 1;
                const float* xn = d_XW0 + ((size_t)(dir * TT + t2) * NB + b) * 96;
                nr = xn[lane]; nu = xn[32 + lane]; nc = xn[64 + lane];
            }
            __syncwarp();
            hbuf[lane] = h;
            __syncwarp();
            u64t ar2 = pack2(xr, 0.0f), au2 = pack2(xu, 0.0f);
            #pragma unroll
            for (int k2 = 0; k2 < 16; k2++) {
                u64t hp = *(const u64t*)(hbuf + 2 * k2);
                ar2 = fma2(*(const u64t*)(g0r + (k2 * 32 + lane) * 2), hp, ar2);
                au2 = fma2(*(const u64t*)(g0u + (k2 * 32 + lane) * 2), hp, au2);
            }
            float arl, arh, aul, auh;
            unpack2(ar2, arl, arh); unpack2(au2, aul, auh);
            float rg = sigf(arl + arh), ug = sigf(aul + auh);
            float rh = rg * h;
            hbuf[36 + lane] = rh;
            __syncwarp();
            u64t ac2 = pack2(xc, 0.0f);
            #pragma unroll
            for (int k2 = 0; k2 < 16; k2++) {
                u64t rp = *(const u64t*)(hbuf + 36 + 2 * k2);
                ac2 = fma2(*(const u64t*)(c0w + (k2 * 32 + lane) * 2), rp, ac2);
            }
            float acl, ach; unpack2(ac2, acl, ach);
            float c = tanhx(acl + ach);
            h = fmaf(ug, h - c, c);
            yrow[(dir * 32 + lane) * 22 + t] = h;
        }
    }
    __syncthreads();

    // ---- xw1 GEMV: t-paired f32x2, two passes over k to cap registers ----
    float accr_s[21], accu_s[21], accc_s[21];   // dynamically indexed -> local
    {
        const float* w1 = sm + SM_W1X + dir * 6144;
        float br = sm[SM_B1 + dir * 96 + lane];
        float bu = sm[SM_B1 + dir * 96 + 32 + lane];
        float bc = sm[SM_B1 + dir * 96 + 64 + lane];

        // pass A: t-pairs 0..4 (t = 0..9)
        {
            u64t ar2[5], au2[5], ac2[5];
            #pragma unroll
            for (int tp = 0; tp < 5; tp++) {
                ar2[tp] = pack2(br, br); au2[tp] = pack2(bu, bu); ac2[tp] = pack2(bc, bc);
            }
            for (int k = 0; k < 64; k++) {
                float wr = w1[k * 96 + lane];
                float wu = w1[k * 96 + 32 + lane];
                float wc = w1[k * 96 + 64 + lane];
                u64t wr2 = pack2(wr, wr), wu2 = pack2(wu, wu), wc2 = pack2(wc, wc);
                const u64t* yk = (const u64t*)(yrow + k * 22);
                #pragma unroll
                for (int tp = 0; tp < 5; tp++) {
                    u64t yp = yk[tp];
                    ar2[tp] = fma2(wr2, yp, ar2[tp]);
                    au2[tp] = fma2(wu2, yp, au2[tp]);
                    ac2[tp] = fma2(wc2, yp, ac2[tp]);
                }
            }
            if (dir == 0) {
                #pragma unroll
                for (int tp = 0; tp < 5; tp++) {
                    unpack2(ar2[tp], accr_s[2 * tp], accr_s[2 * tp + 1]);
                    unpack2(au2[tp], accu_s[2 * tp], accu_s[2 * tp + 1]);
                    unpack2(ac2[tp], accc_s[2 * tp], accc_s[2 * tp + 1]);
                }
            } else {
                #pragma unroll
                for (int tp = 0; tp < 5; tp++) {
                    unpack2(ar2[tp], accr_s[20 - 2 * tp], accr_s[19 - 2 * tp]);
                    unpack2(au2[tp], accu_s[20 - 2 * tp], accu_s[19 - 2 * tp]);
                    unpack2(ac2[tp], accc_s[20 - 2 * tp], accc_s[19 - 2 * tp]);
                }
            }
        }
        // pass B: t-pairs 5..9 (t = 10..19) + scalar t = 20
        {
            u64t ar2[5], au2[5], ac2[5];
            float ar20 = br, au20 = bu, ac20 = bc;
            #pragma unroll
            for (int tp = 0; tp < 5; tp++) {
                ar2[tp] = pack2(br, br); au2[tp] = pack2(bu, bu); ac2[tp] = pack2(bc, bc);
            }
            for (int k = 0; k < 64; k++) {
                float wr = w1[k * 96 + lane];
                float wu = w1[k * 96 + 32 + lane];
                float wc = w1[k * 96 + 64 + lane];
                u64t wr2 = pack2(wr, wr), wu2 = pack2(wu, wu), wc2 = pack2(wc, wc);
                const u64t* yk = (const u64t*)(yrow + k * 22);
                #pragma unroll
                for (int tp = 0; tp < 5; tp++) {
                    u64t yp = yk[5 + tp];
                    ar2[tp] = fma2(wr2, yp, ar2[tp]);
                    au2[tp] = fma2(wu2, yp, au2[tp]);
                    ac2[tp] = fma2(wc2, yp, ac2[tp]);
                }
                float y20 = yrow[k * 22 + 20];
                ar20 = fmaf(wr, y20, ar20);
                au20 = fmaf(wu, y20, au20);
                ac20 = fmaf(wc, y20, ac20);
            }
            if (dir == 0) {
                #pragma unroll
                for (int tp = 0; tp < 5; tp++) {
                    unpack2(ar2[tp], accr_s[10 + 2 * tp], accr_s[11 + 2 * tp]);
                    unpack2(au2[tp], accu_s[10 + 2 * tp], accu_s[11 + 2 * tp]);
                    unpack2(ac2[tp], accc_s[10 + 2 * tp], accc_s[11 + 2 * tp]);
                }
                accr_s[20] = ar20; accu_s[20] = au20; accc_s[20] = ac20;
            } else {
                #pragma unroll
                for (int tp = 0; tp < 5; tp++) {
                    // t = 10+2tp -> s = 20-t = 10-2tp;  t+1 -> s-1
                    unpack2(ar2[tp], accr_s[10 - 2 * tp], accr_s[9 - 2 * tp]);
                    unpack2(au2[tp], accu_s[10 - 2 * tp], accu_s[9 - 2 * tp]);
                    unpack2(ac2[tp], accc_s[10 - 2 * tp], accc_s[9 - 2 * tp]);
                }
                accr_s[0] = ar20; accu_s[0] = au20; accc_s[0] = ac20;
            }
        }
    }

    // ---- layer1 recurrence (rolled; acc in local, trivial traffic) ----
    {
        const float* g1r = sm + SM_G1R + dir * 1024;
        const float* g1u = sm + SM_G1U + dir * 1024;
        const float* c1w = sm + SM_C1  + dir * 1024;
        float h = 0.0f;
        for (int s = 0; s < 21; s++) {
            float xr = accr_s[s], xu = accu_s[s], xc = accc_s[s];
            __syncwarp();
            hbuf[lane] = h;
            __syncwarp();
            u64t ar2 = pack2(xr, 0.0f), au2 = pack2(xu, 0.0f);
            #pragma unroll
            for (int k2 = 0; k2 < 16; k2++) {
                u64t hp = *(const u64t*)(hbuf + 2 * k2);
                ar2 = fma2(*(const u64t*)(g1r + (k2 * 32 + lane) * 2), hp, ar2);
                au2 = fma2(*(const u64t*)(g1u + (k2 * 32 + lane) * 2), hp, au2);
            }
            float arl, arh, aul, auh;
            unpack2(ar2, arl, arh); unpack2(au2, aul, auh);
            float rg = sigf(arl + arh), ug = sigf(aul + auh);
            float rh = rg * h;
            hbuf[36 + lane] = rh;
            __syncwarp();
            u64t ac2 = pack2(xc, 0.0f);
            #pragma unroll
            for (int k2 = 0; k2 < 16; k2++) {
                u64t rp = *(const u64t*)(hbuf + 36 + 2 * k2);
                ac2 = fma2(*(const u64t*)(c1w + (k2 * 32 + lane) * 2), rp, ac2);
            }
            float acl, ach; unpack2(ac2, acl, ach);
            float c = tanhx(acl + ach);
            h = fmaf(ug, h - c, c);
            int t = dir ? 20 - s : s;
            out[((size_t)b * TT + t) * 64 + dir * 32 + lane] = h;
        }
    }
}

// ---------------- launch ----------------------------------------------------
extern "C" void kernel_launch(void* const* d_in, const int* in_sizes, int n_in,
                              void* d_out, int out_size)
{
    const int*   tok_b = (const int*)d_in[0];
    const int*   typ_b = (const int*)d_in[1];
    const void*  msk_b = (const void*)d_in[2];
    const int*   tok_a = (const int*)d_in[3];
    const int*   typ_a = (const int*)d_in[4];
    const void*  msk_a = (const void*)d_in[5];
    const float* temb = (const float*)d_in[6];
    const float* yemb = (const float*)d_in[7];
    const float* hole = (const float*)d_in[8];
    const float* gk_fw0 = (const float*)d_in[9];
    const float* gb_fw0 = (const float*)d_in[10];
    const float* ck_fw0 = (const float*)d_in[11];
    const float* cb_fw0 = (const float*)d_in[12];
    const float* gk_bw0 = (const float*)d_in[13];
    const float* gb_bw0 = (const float*)d_in[14];
    const float* ck_bw0 = (const float*)d_in[15];
    const float* cb_bw0 = (const float*)d_in[16];
    const float* gk_fw1 = (const float*)d_in[17];
    const float* gb_fw1 = (const float*)d_in[18];
    const float* ck_fw1 = (const float*)d_in[19];
    const float* cb_fw1 = (const float*)d_in[20];
    const float* gk_bw1 = (const float*)d_in[21];
    const float* gb_bw1 = (const float*)d_in[22];
    const float* ck_bw1 = (const float*)d_in[23];
    const float* cb_bw1 = (const float*)d_in[24];
    float* out = (float*)d_out;

    cudaFuncSetAttribute(k_fused, cudaFuncAttributeMaxDynamicSharedMemorySize, SM_BYTES);

    // 0) detect mask dtype (uint8 vs int32 vs float32)
    k_reset<<<1, 1>>>();
    k_detect<<<148, 256>>>((const unsigned*)msk_b);

    // 1) token table (tiled GEMM) + hole row
    k_tables2<<<79, 256>>>(temb,
                           gk_fw0, gb_fw0, ck_fw0, cb_fw0,
                           gk_bw0, gb_bw0, ck_bw0, cb_bw0);
    k_hole<<<1, 192>>>(hole,
                       gk_fw0, gb_fw0, ck_fw0, cb_fw0,
                       gk_bw0, gb_bw0, ck_bw0, cb_bw0);

    // 2) layer0 x-precompute, typemax fused, both dirs per block
    k_xw0<<<2688, 256>>>(tok_b, tok_a,
                         typ_b, msk_b, typ_a, msk_a, yemb,
                         gk_fw0 + 128 * 64, ck_fw0 + 128 * 32,
                         gk_bw0 + 128 * 64, ck_bw0 + 128 * 32);

    // 3) fused: layer0 recurrence -> xw1 GEMV -> layer1 recurrence -> out
    k_fused<<<512, 1024, SM_BYTES>>>(gk_fw0, ck_fw0, gk_bw0, ck_bw0,
                                     gk_fw1, gb_fw1, ck_fw1, cb_fw1,
                                     gk_bw1, gb_bw1, ck_bw1, cb_bw1,
                                     out);
}

// round 12
// speedup vs baseline: 1.2642x; 1.2642x over previous
#include <cuda_runtime.h>
#include <math.h>

#define NB 8192
#define TT 21

// ---------------- scratch (static device allocations; no cudaMalloc) -------
__device__ float d_TW[5056 * 192];      // token-part of layer0 x@Wx (+bias), per dir
__device__ float d_HW[2 * 96];          // hole row x@Wx (+bias), per dir
__device__ float d_XW0[2 * TT * NB * 96];
__device__ unsigned d_maskFlags;        // dtype-detection flags for mask buffers

// ---------------- f32x2 helpers --------------------------------------------
typedef unsigned long long u64t;
__device__ __forceinline__ u64t pack2(float lo, float hi) {
    u64t r; asm("mov.b64 %0,{%1,%2};" : "=l"(r) : "f"(lo), "f"(hi)); return r;
}
__device__ __forceinline__ void unpack2(u64t v, float& lo, float& hi) {
    asm("mov.b64 {%0,%1},%2;" : "=f"(lo), "=f"(hi) : "l"(v));
}
__device__ __forceinline__ u64t fma2(u64t a, u64t b, u64t c) {
    u64t d; asm("fma.rn.f32x2 %0,%1,%2,%3;" : "=l"(d) : "l"(a), "l"(b), "l"(c)); return d;
}
__device__ __forceinline__ float sigf(float x)  { return 1.0f / (1.0f + __expf(-x)); }
__device__ __forceinline__ float tanhx(float x) { return 1.0f - 2.0f / (__expf(2.0f * x) + 1.0f); }

// ---------------- K0: mask dtype detection ---------------------------------
__global__ void k_reset() { d_maskFlags = 0u; }

__global__ void k_detect(const unsigned* __restrict__ m) {
    unsigned f = 0;
    for (int i = blockIdx.x * blockDim.x + threadIdx.x; i < 204800;
         i += gridDim.x * blockDim.x) {
        unsigned w = m[i];
        if (w != 0u && w != 1u) f |= 1u;
        if (w != 0u && w != 0x3F800000u) f |= 2u;
    }
    if (f) atomicOr(&d_maskFlags, f);
}

// ---------------- K1: token table tiled GEMM; block 79 = hole row ----------
__global__ void k_tables2(const float* __restrict__ tok_emb,
                          const float* __restrict__ hole,
                          const float* __restrict__ gk_fw, const float* __restrict__ gb_fw,
                          const float* __restrict__ ck_fw, const float* __restrict__ cb_fw,
                          const float* __restrict__ gk_bw, const float* __restrict__ gb_bw,
                          const float* __restrict__ ck_bw, const float* __restrict__ cb_bw)
{
    __shared__ float sA[64][33];
    __shared__ float sW[32][192];
    __shared__ float sB[192];
    int tid = threadIdx.x, tx = tid & 15, ty = tid >> 4;

    if (blockIdx.x == 79) {              // hole row, full 160-dim input
        __shared__ float s[160];
        if (tid < 160) s[tid] = hole[tid];
        __syncthreads();
        if (tid < 192) {
            int dir = tid / 96, col = tid % 96;
            const float* gk = dir ? gk_bw : gk_fw;
            const float* ck = dir ? ck_bw : ck_fw;
            const float* gb = dir ? gb_bw : gb_fw;
            const float* cb = dir ? cb_bw : cb_fw;
            const float* w;
            int stride;
            float acc;
            if (col < 64) { w = gk + col;        stride = 64; acc = gb[col]; }
            else          { w = ck + (col - 64); stride = 32; acc = cb[col - 64]; }
            #pragma unroll 8
            for (int k = 0; k < 160; k++) acc = fmaf(s[k], w[k * stride], acc);
            d_HW[tid] = acc;
        }
        return;
    }

    int b0 = blockIdx.x * 64;
    if (tid < 192) {
        int d = tid / 96, c = tid % 96;
        sB[tid] = (c < 64) ? (d ? gb_bw : gb_fw)[c] : (d ? cb_bw : cb_fw)[c - 64];
    }
    __syncthreads();

    float acc[4][12];
    #pragma unroll
    for (int c = 0; c < 12; c++) {
        float bv = sB[tx + 16 * c];
        #pragma unroll
        for (int r = 0; r < 4; r++) acc[r][c] = bv;
    }

    for (int kc = 0; kc < 4; kc++) {
        for (int i = tid; i < 64 * 32; i += 256) {
            int row = i >> 5, kk = i & 31;
            int v = b0 + row;
            sA[row][kk] = (v < 5000) ? tok_emb[v * 128 + kc * 32 + kk] : 0.0f;
        }
        for (int i = tid; i < 32 * 192; i += 256) {
            int k = i / 192, c = i % 192, d = c / 96, cc = c % 96;
            const float* gkp = d ? gk_bw : gk_fw;
            const float* ckp = d ? ck_bw : ck_fw;
            int row = kc * 32 + k;
            sW[k][c] = (cc < 64) ? gkp[row * 64 + cc] : ckp[row * 32 + (cc - 64)];
        }
        __syncthreads();
        #pragma unroll
        for (int k = 0; k < 32; k++) {
            float a[4];
            #pragma unroll
            for (int r = 0; r < 4; r++) a[r] = sA[ty * 4 + r][k];
            #pragma unroll
            for (int c = 0; c < 12; c++) {
                float bv = sW[k][tx + 16 * c];
                #pragma unroll
                for (int r = 0; r < 4; r++) acc[r][c] = fmaf(a[r], bv, acc[r][c]);
            }
        }
        __syncthreads();
    }

    #pragma unroll
    for (int r = 0; r < 4; r++) {
        int v = b0 + ty * 4 + r;
        if (v < 5000)
            #pragma unroll
            for (int c = 0; c < 12; c++)
                d_TW[(size_t)v * 192 + tx + 16 * c] = acc[r][c];
    }
}

// ---------------- K2: layer0 x-precompute GEMM, typemax fused, both dirs ---
__global__ void k_xw0(const int* __restrict__ tok_b, const int* __restrict__ tok_a,
                      const int* __restrict__ typ_b, const void* __restrict__ msk_b,
                      const int* __restrict__ typ_a, const void* __restrict__ msk_a,
                      const float* __restrict__ yemb,
                      const float* __restrict__ gkx_fw, const float* __restrict__ ckx_fw,
                      const float* __restrict__ gkx_bw, const float* __restrict__ ckx_bw)
{
    __shared__ float sA[64][33];
    __shared__ float sW[32][96];
    __shared__ int   sTok[64];
    int rt  = blockIdx.x;                // 0..2687
    int t   = rt >> 7;
    int b0  = (rt & 127) << 6;
    int tid = threadIdx.x;
    int tx = tid & 15, ty = tid >> 4;

    if (t == 10) {                       // hole: identical row for all b
        for (int dir = 0; dir < 2; dir++) {
            float* outp = d_XW0 + ((size_t)(dir * TT + t) * NB + b0) * 96;
            #pragma unroll
            for (int c = 0; c < 6; c++) {
                int col = tx + 16 * c;
                float v = d_HW[dir * 96 + col];
                #pragma unroll
                for (int r = 0; r < 4; r++) outp[(ty * 4 + r) * 96 + col] = v;
            }
        }
        return;
    }

    // ---- fused masked type-max (computed ONCE, shared by both dirs) ----
    {
        unsigned flags = d_maskFlags;
        int mode = ((flags & 1u) == 0u) ? 1 : (((flags & 2u) == 0u) ? 2 : 0);
        int wid = tid >> 5, lane = tid & 31;
        int pos = (t < 10) ? t : t - 11;
        const int*  typ = (t < 10) ? typ_b : typ_a;
        const void* msk = (t < 10) ? msk_b : msk_a;
        for (int rr = wid; rr < 64; rr += 8) {
            int bb = b0 + rr;
            int base = (bb * 10 + pos) * 10;
            float m = -3.402823e38f;
            #pragma unroll
            for (int nt = 0; nt < 10; nt++) {
                int id = typ[base + nt];
                bool valid;
                if (mode == 1)      valid = ((const int*)msk)[base + nt] != 0;
                else if (mode == 2) valid = ((const float*)msk)[base + nt] != 0.0f;
                else                valid = ((const unsigned char*)msk)[base + nt] != 0;
                m = fmaxf(m, yemb[id * 32 + lane] + (valid ? 0.0f : -1000.0f));
            }
            sA[rr][lane] = m;
        }
    }
    if (tid < 64) {
        int bb = b0 + tid;
        sTok[tid] = (t < 10) ? tok_b[bb * 10 + t] : tok_a[bb * 10 + (t - 11)];
    }

    for (int dir = 0; dir < 2; dir++) {
        const float* gkx = dir ? gkx_bw : gkx_fw;
        const float* ckx = dir ? ckx_bw : ckx_fw;
        for (int i = tid; i < 32 * 64; i += 256) sW[i >> 6][i & 63]        = gkx[i];
        for (int i = tid; i < 32 * 32; i += 256) sW[i >> 5][64 + (i & 31)] = ckx[i];
        __syncthreads();

        float acc[4][6];
        #pragma unroll
        for (int r = 0; r < 4; r++)
            #pragma unroll
            for (int c = 0; c < 6; c++) acc[r][c] = 0.0f;

        #pragma unroll
        for (int k = 0; k < 32; k++) {
            float a[4], bv[6];
            #pragma unroll
            for (int r = 0; r < 4; r++) a[r] = sA[ty * 4 + r][k];
            #pragma unroll
            for (int c = 0; c < 6; c++) bv[c] = sW[k][tx + 16 * c];
            #pragma unroll
            for (int r = 0; r < 4; r++)
                #pragma unroll
                for (int c = 0; c < 6; c++) acc[r][c] = fmaf(a[r], bv[c], acc[r][c]);
        }

        float* outp = d_XW0 + ((size_t)(dir * TT + t) * NB + b0) * 96;
        #pragma unroll
        for (int r = 0; r < 4; r++) {
            const float* tw = d_TW + (size_t)sTok[ty * 4 + r] * 192 + dir * 96;
            #pragma unroll
            for (int c = 0; c < 6; c++) {
                int col = tx + 16 * c;
                outp[(ty * 4 + r) * 96 + col] = acc[r][c] + tw[col];
            }
        }
        __syncthreads();                 // before restaging sW for next dir
    }
}

// ---------------- K3: fused recurrence, 2 rows per warp --------------------
// 512 threads = 16 warps; warp = (dir, rowpair); 16 batch rows per block.
// smem (floats):
//  G0R/G0U/C0, G1R/G1U/C1: k-paired rec weights [dir][k2][lane][2]  6 x 2048
//  W1X: layer1 x-part [dir][64][96]                                 12288
//  B1:  layer1 bias [dir][96]                                       192
//  Y:   layer0 output, channel-major [16 rows][64 ch][22]           22528
//  H:   per-warp broadcast: hA@0 hB@36 rhA@72 rhB@108  [16][144]    2304
#define SM_G0R 0
#define SM_G0U 2048
#define SM_C0  4096
#define SM_G1R 6144
#define SM_G1U 8192
#define SM_C1  10240
#define SM_W1X 12288
#define SM_B1  24576
#define SM_Y   24768
#define SM_H   47296
#define SM_TOTF 49600
#define SM_BYTES (SM_TOTF * 4)

__global__ __launch_bounds__(512, 1)
void k_fused(const float* __restrict__ gk_fw0, const float* __restrict__ ck_fw0,
             const float* __restrict__ gk_bw0, const float* __restrict__ ck_bw0,
             const float* __restrict__ gk_fw1, const float* __restrict__ gb_fw1,
             const float* __restrict__ ck_fw1, const float* __restrict__ cb_fw1,
             const float* __restrict__ gk_bw1, const float* __restrict__ gb_bw1,
             const float* __restrict__ ck_bw1, const float* __restrict__ cb_bw1,
             float* __restrict__ out)
{
    extern __shared__ float sm[];
    int tid = threadIdx.x;

    // ---- stage all weights once (k-paired layouts for rec) ----
    for (int i = tid; i < 2048; i += 512) {
        int p = i & 1, ln = (i >> 1) & 31, k2 = (i >> 6) & 15, d = i >> 10;
        const float* gk0 = d ? gk_bw0 : gk_fw0;
        const float* ck0 = d ? ck_bw0 : ck_fw0;
        const float* gk1 = d ? gk_bw1 : gk_fw1;
        const float* ck1 = d ? ck_bw1 : ck_fw1;
        int r0 = 160 + 2 * k2 + p;       // layer0 h-part rows
        int r1 = 64 + 2 * k2 + p;        // layer1 h-part rows
        sm[SM_G0R + i] = gk0[r0 * 64 + ln];
        sm[SM_G0U + i] = gk0[r0 * 64 + 32 + ln];
        sm[SM_C0  + i] = ck0[r0 * 32 + ln];
        sm[SM_G1R + i] = gk1[r1 * 64 + ln];
        sm[SM_G1U + i] = gk1[r1 * 64 + 32 + ln];
        sm[SM_C1  + i] = ck1[r1 * 32 + ln];
    }
    for (int i = tid; i < 12288; i += 512) {
        int d = i / 6144, rem = i % 6144, k = rem / 96, c = rem % 96;
        const float* gk1 = d ? gk_bw1 : gk_fw1;
        const float* ck1 = d ? ck_bw1 : ck_fw1;
        sm[SM_W1X + i] = (c < 64) ? gk1[k * 64 + c] : ck1[k * 32 + (c - 64)];
    }
    if (tid < 192) {
        int d = tid / 96, c = tid % 96;
        sm[SM_B1 + tid] = (c < 64) ? (d ? gb_bw1 : gb_fw1)[c]
                                   : (d ? cb_bw1 : cb_fw1)[c - 64];
    }
    __syncthreads();

    int lane = tid & 31, wid = tid >> 5;
    int dir = wid >> 3, rp = wid & 7;
    int rA = rp * 2, rB = rA + 1;
    int bA = blockIdx.x * 16 + rA;       // bB = bA + 1
    float* yA = sm + SM_Y + rA * 1408;   // [64 ch][22]
    float* yB = sm + SM_Y + rB * 1408;
    float* hbuf = sm + SM_H + wid * 144; // hA@0 hB@36 rhA@72 rhB@108
    const float* g0r = sm + SM_G0R + dir * 1024;
    const float* g0u = sm + SM_G0U + dir * 1024;
    const float* c0w = sm + SM_C0  + dir * 1024;

    // ---- layer0 recurrence, 2 rows interleaved; Y channel-major in smem ----
    {
        float hA = 0.0f, hB = 0.0f;
        int t0 = dir ? 20 : 0;
        const float* xw = d_XW0 + ((size_t)(dir * TT + t0) * NB + bA) * 96;
        float nrA = xw[lane],      nuA = xw[32 + lane],  ncA = xw[64 + lane];
        float nrB = xw[96 + lane], nuB = xw[128 + lane], ncB = xw[160 + lane];
        for (int s = 0; s < 21; s++) {
            int t = dir ? 20 - s : s;
            float xrA = nrA, xuA = nuA, xcA = ncA;
            float xrB = nrB, xuB = nuB, xcB = ncB;
            if (s < 20) {
                int t2 = dir ? t - 1 : t + 1;
                const float* xn = d_XW0 + ((size_t)(dir * TT + t2) * NB + bA) * 96;
                nrA = xn[lane];      nuA = xn[32 + lane];  ncA = xn[64 + lane];
                nrB = xn[96 + lane]; nuB = xn[128 + lane]; ncB = xn[160 + lane];
            }
            __syncwarp();
            hbuf[lane] = hA;
            hbuf[36 + lane] = hB;
            __syncwarp();
            u64t arA = pack2(xrA, 0.0f), auA = pack2(xuA, 0.0f);
            u64t arB = pack2(xrB, 0.0f), auB = pack2(xuB, 0.0f);
            #pragma unroll
            for (int k2 = 0; k2 < 16; k2++) {
                u64t hpA = *(const u64t*)(hbuf + 2 * k2);
                u64t hpB = *(const u64t*)(hbuf + 36 + 2 * k2);
                u64t wr = *(const u64t*)(g0r + (k2 * 32 + lane) * 2);
                u64t wu = *(const u64t*)(g0u + (k2 * 32 + lane) * 2);
                arA = fma2(wr, hpA, arA); arB = fma2(wr, hpB, arB);
                auA = fma2(wu, hpA, auA); auB = fma2(wu, hpB, auB);
            }
            float l0, l1;
            unpack2(arA, l0, l1); float rgA = sigf(l0 + l1);
            unpack2(auA, l0, l1); float ugA = sigf(l0 + l1);
            unpack2(arB, l0, l1); float rgB = sigf(l0 + l1);
            unpack2(auB, l0, l1); float ugB = sigf(l0 + l1);
            float rhA = rgA * hA, rhB = rgB * hB;
            hbuf[72 + lane]  = rhA;
            hbuf[108 + lane] = rhB;
            __syncwarp();
            u64t acA = pack2(xcA, 0.0f), acB = pack2(xcB, 0.0f);
            #pragma unroll
            for (int k2 = 0; k2 < 16; k2++) {
                u64t rpA = *(const u64t*)(hbuf + 72 + 2 * k2);
                u64t rpB = *(const u64t*)(hbuf + 108 + 2 * k2);
                u64t wc = *(const u64t*)(c0w + (k2 * 32 + lane) * 2);
                acA = fma2(wc, rpA, acA); acB = fma2(wc, rpB, acB);
            }
            unpack2(acA, l0, l1); float cA = tanhx(l0 + l1);
            unpack2(acB, l0, l1); float cB = tanhx(l0 + l1);
            hA = fmaf(ugA, hA - cA, cA);
            hB = fmaf(ugB, hB - cB, cB);
            yA[(dir * 32 + lane) * 22 + t] = hA;
            yB[(dir * 32 + lane) * 22 + t] = hB;
        }
    }
    __syncthreads();

    // ---- xw1 GEMV: t-paired f32x2 over channel-major Y, per-row pass ----
    float accr_s[2][21], accu_s[2][21], accc_s[2][21];  // local (dyn-indexed)
    {
        const float* w1 = sm + SM_W1X + dir * 6144;
        float br = sm[SM_B1 + dir * 96 + lane];
        float bu = sm[SM_B1 + dir * 96 + 32 + lane];
        float bc = sm[SM_B1 + dir * 96 + 64 + lane];
        #pragma unroll
        for (int rr = 0; rr < 2; rr++) {
            const float* yrow = rr ? yB : yA;
            u64t ar2[10], au2[10], ac2[10];
            float ar20 = br, au20 = bu, ac20 = bc;
            #pragma unroll
            for (int tp = 0; tp < 10; tp++) {
                ar2[tp] = pack2(br, br); au2[tp] = pack2(bu, bu); ac2[tp] = pack2(bc, bc);
            }
            for (int k = 0; k < 64; k++) {
                float wr = w1[k * 96 + lane];
                float wu = w1[k * 96 + 32 + lane];
                float wc = w1[k * 96 + 64 + lane];
                u64t wr2 = pack2(wr, wr), wu2 = pack2(wu, wu), wc2 = pack2(wc, wc);
                const u64t* yk = (const u64t*)(yrow + k * 22);
                #pragma unroll
                for (int tp = 0; tp < 10; tp++) {
                    u64t yp = yk[tp];
                    ar2[tp] = fma2(wr2, yp, ar2[tp]);
                    au2[tp] = fma2(wu2, yp, au2[tp]);
                    ac2[tp] = fma2(wc2, yp, ac2[tp]);
                }
                float y20 = yrow[k * 22 + 20];
                ar20 = fmaf(wr, y20, ar20);
                au20 = fmaf(wu, y20, au20);
                ac20 = fmaf(wc, y20, ac20);
            }
            // unpack into step order: step s handles t = dir?20-s:s
            if (dir == 0) {
                #pragma unroll
                for (int tp = 0; tp < 10; tp++) {
                    unpack2(ar2[tp], accr_s[rr][2 * tp], accr_s[rr][2 * tp + 1]);
                    unpack2(au2[tp], accu_s[rr][2 * tp], accu_s[rr][2 * tp + 1]);
                    unpack2(ac2[tp], accc_s[rr][2 * tp], accc_s[rr][2 * tp + 1]);
                }
                accr_s[rr][20] = ar20; accu_s[rr][20] = au20; accc_s[rr][20] = ac20;
            } else {
                #pragma unroll
                for (int tp = 0; tp < 10; tp++) {
                    unpack2(ar2[tp], accr_s[rr][20 - 2 * tp], accr_s[rr][19 - 2 * tp]);
                    unpack2(au2[tp], accu_s[rr][20 - 2 * tp], accu_s[rr][19 - 2 * tp]);
                    unpack2(ac2[tp], accc_s[rr][20 - 2 * tp], accc_s[rr][19 - 2 * tp]);
                }
                accr_s[rr][0] = ar20; accu_s[rr][0] = au20; accc_s[rr][0] = ac20;
            }
        }
    }

    // ---- layer1 recurrence, 2 rows interleaved ----
    {
        const float* g1r = sm + SM_G1R + dir * 1024;
        const float* g1u = sm + SM_G1U + dir * 1024;
        const float* c1w = sm + SM_C1  + dir * 1024;
        float hA = 0.0f, hB = 0.0f;
        for (int s = 0; s < 21; s++) {
            float xrA = accr_s[0][s], xuA = accu_s[0][s], xcA = accc_s[0][s];
            float xrB = accr_s[1][s], xuB = accu_s[1][s], xcB = accc_s[1][s];
            __syncwarp();
            hbuf[lane] = hA;
            hbuf[36 + lane] = hB;
            __syncwarp();
            u64t arA = pack2(xrA, 0.0f), auA = pack2(xuA, 0.0f);
            u64t arB = pack2(xrB, 0.0f), auB = pack2(xuB, 0.0f);
            #pragma unroll
            for (int k2 = 0; k2 < 16; k2++) {
                u64t hpA = *(const u64t*)(hbuf + 2 * k2);
                u64t hpB = *(const u64t*)(hbuf + 36 + 2 * k2);
                u64t wr = *(const u64t*)(g1r + (k2 * 32 + lane) * 2);
                u64t wu = *(const u64t*)(g1u + (k2 * 32 + lane) * 2);
                arA = fma2(wr, hpA, arA); arB = fma2(wr, hpB, arB);
                auA = fma2(wu, hpA, auA); auB = fma2(wu, hpB, auB);
            }
            float l0, l1;
            unpack2(arA, l0, l1); float rgA = sigf(l0 + l1);
            unpack2(auA, l0, l1); float ugA = sigf(l0 + l1);
            unpack2(arB, l0, l1); float rgB = sigf(l0 + l1);
            unpack2(auB, l0, l1); float ugB = sigf(l0 + l1);
            float rhA = rgA * hA, rhB = rgB * hB;
            hbuf[72 + lane]  = rhA;
            hbuf[108 + lane] = rhB;
            __syncwarp();
            u64t acA = pack2(xcA, 0.0f), acB = pack2(xcB, 0.0f);
            #pragma unroll
            for (int k2 = 0; k2 < 16; k2++) {
                u64t rpA = *(const u64t*)(hbuf + 72 + 2 * k2);
                u64t rpB = *(const u64t*)(hbuf + 108 + 2 * k2);
                u64t wc = *(const u64t*)(c1w + (k2 * 32 + lane) * 2);
                acA = fma2(wc, rpA, acA); acB = fma2(wc, rpB, acB);
            }
            unpack2(acA, l0, l1); float cA = tanhx(l0 + l1);
            unpack2(acB, l0, l1); float cB = tanhx(l0 + l1);
            hA = fmaf(ugA, hA - cA, cA);
            hB = fmaf(ugB, hB - cB, cB);
            int t = dir ? 20 - s : s;
            out[((size_t)bA * TT + t) * 64 + dir * 32 + lane] = hA;
            out[((size_t)(bA + 1) * TT + t) * 64 + dir * 32 + lane] = hB;
        }
    }
}

// ---------------- launch ----------------------------------------------------
extern "C" void kernel_launch(void* const* d_in, const int* in_sizes, int n_in,
                              void* d_out, int out_size)
{
    const int*   tok_b = (const int*)d_in[0];
    const int*   typ_b = (const int*)d_in[1];
    const void*  msk_b = (const void*)d_in[2];
    const int*   tok_a = (const int*)d_in[3];
    const int*   typ_a = (const int*)d_in[4];
    const void*  msk_a = (const void*)d_in[5];
    const float* temb = (const float*)d_in[6];
    const float* yemb = (const float*)d_in[7];
    const float* hole = (const float*)d_in[8];
    const float* gk_fw0 = (const float*)d_in[9];
    const float* gb_fw0 = (const float*)d_in[10];
    const float* ck_fw0 = (const float*)d_in[11];
    const float* cb_fw0 = (const float*)d_in[12];
    const float* gk_bw0 = (const float*)d_in[13];
    const float* gb_bw0 = (const float*)d_in[14];
    const float* ck_bw0 = (const float*)d_in[15];
    const float* cb_bw0 = (const float*)d_in[16];
    const float* gk_fw1 = (const float*)d_in[17];
    const float* gb_fw1 = (const float*)d_in[18];
    const float* ck_fw1 = (const float*)d_in[19];
    const float* cb_fw1 = (const float*)d_in[20];
    const float* gk_bw1 = (const float*)d_in[21];
    const float* gb_bw1 = (const float*)d_in[22];
    const float* ck_bw1 = (const float*)d_in[23];
    const float* cb_bw1 = (const float*)d_in[24];
    float* out = (float*)d_out;

    cudaFuncSetAttribute(k_fused, cudaFuncAttributeMaxDynamicSharedMemorySize, SM_BYTES);

    // 0) detect mask dtype (uint8 vs int32 vs float32)
    k_reset<<<1, 1>>>();
    k_detect<<<148, 256>>>((const unsigned*)msk_b);

    // 1) token table (tiled GEMM) with hole row as block 79
    k_tables2<<<80, 256>>>(temb, hole,
                           gk_fw0, gb_fw0, ck_fw0, cb_fw0,
                           gk_bw0, gb_bw0, ck_bw0, cb_bw0);

    // 2) layer0 x-precompute, typemax fused, both dirs per block
    k_xw0<<<2688, 256>>>(tok_b, tok_a,
                         typ_b, msk_b, typ_a, msk_a, yemb,
                         gk_fw0 + 128 * 64, ck_fw0 + 128 * 32,
                         gk_bw0 + 128 * 64, ck_bw0 + 128 * 32);

    // 3) fused: layer0 rec -> xw1 GEMV -> layer1 rec, 2 rows per warp
    k_fused<<<512, 512, SM_BYTES>>>(gk_fw0, ck_fw0, gk_bw0, ck_bw0,
                                    gk_fw1, gb_fw1, ck_fw1, cb_fw1,
                                    gk_bw1, gb_bw1, ck_bw1, cb_bw1,
                                    out);
}

// round 13
// speedup vs baseline: 1.2953x; 1.0246x over previous
#include <cuda_runtime.h>
#include <math.h>

#define NB 8192
#define TT 21

// ---------------- scratch (static device allocations; no cudaMalloc) -------
__device__ float d_TW[5056 * 192];      // token-part of layer0 x@Wx (+bias), per dir
__device__ float d_HW[2 * 96];          // hole row x@Wx (+bias), per dir
__device__ float d_XW0[2 * TT * NB * 96];
__device__ unsigned d_maskFlags;        // dtype-detection flags for mask buffers

// ---------------- f32x2 helpers --------------------------------------------
typedef unsigned long long u64t;
__device__ __forceinline__ u64t pack2(float lo, float hi) {
    u64t r; asm("mov.b64 %0,{%1,%2};" : "=l"(r) : "f"(lo), "f"(hi)); return r;
}
__device__ __forceinline__ void unpack2(u64t v, float& lo, float& hi) {
    asm("mov.b64 {%0,%1},%2;" : "=f"(lo), "=f"(hi) : "l"(v));
}
__device__ __forceinline__ u64t fma2(u64t a, u64t b, u64t c) {
    u64t d; asm("fma.rn.f32x2 %0,%1,%2,%3;" : "=l"(d) : "l"(a), "l"(b), "l"(c)); return d;
}
__device__ __forceinline__ u64t add2(u64t a, u64t b) {
    u64t d; asm("add.rn.f32x2 %0,%1,%2;" : "=l"(d) : "l"(a), "l"(b)); return d;
}
__device__ __forceinline__ float sigf(float x)  { return 1.0f / (1.0f + __expf(-x)); }
__device__ __forceinline__ float tanhx(float x) { return 1.0f - 2.0f / (__expf(2.0f * x) + 1.0f); }

// ---------------- K0: mask dtype detection ---------------------------------
__global__ void k_reset() { d_maskFlags = 0u; }

__global__ void k_detect(const unsigned* __restrict__ m) {
    unsigned f = 0;
    for (int i = blockIdx.x * blockDim.x + threadIdx.x; i < 204800;
         i += gridDim.x * blockDim.x) {
        unsigned w = m[i];
        if (w != 0u && w != 1u) f |= 1u;
        if (w != 0u && w != 0x3F800000u) f |= 2u;
    }
    if (f) atomicOr(&d_maskFlags, f);
}

// ---------------- K1: token table tiled GEMM; block 79 = hole row ----------
__global__ void k_tables2(const float* __restrict__ tok_emb,
                          const float* __restrict__ hole,
                          const float* __restrict__ gk_fw, const float* __restrict__ gb_fw,
                          const float* __restrict__ ck_fw, const float* __restrict__ cb_fw,
                          const float* __restrict__ gk_bw, const float* __restrict__ gb_bw,
                          const float* __restrict__ ck_bw, const float* __restrict__ cb_bw)
{
    __shared__ float sA[64][33];
    __shared__ float sW[32][192];
    __shared__ float sB[192];
    int tid = threadIdx.x, tx = tid & 15, ty = tid >> 4;

    if (blockIdx.x == 79) {              // hole row, full 160-dim input
        __shared__ float s[160];
        if (tid < 160) s[tid] = hole[tid];
        __syncthreads();
        if (tid < 192) {
            int dir = tid / 96, col = tid % 96;
            const float* gk = dir ? gk_bw : gk_fw;
            const float* ck = dir ? ck_bw : ck_fw;
            const float* gb = dir ? gb_bw : gb_fw;
            const float* cb = dir ? cb_bw : cb_fw;
            const float* w;
            int stride;
            float acc;
            if (col < 64) { w = gk + col;        stride = 64; acc = gb[col]; }
            else          { w = ck + (col - 64); stride = 32; acc = cb[col - 64]; }
            #pragma unroll 8
            for (int k = 0; k < 160; k++) acc = fmaf(s[k], w[k * stride], acc);
            d_HW[tid] = acc;
        }
        return;
    }

    int b0 = blockIdx.x * 64;
    if (tid < 192) {
        int d = tid / 96, c = tid % 96;
        sB[tid] = (c < 64) ? (d ? gb_bw : gb_fw)[c] : (d ? cb_bw : cb_fw)[c - 64];
    }
    __syncthreads();

    float acc[4][12];
    #pragma unroll
    for (int c = 0; c < 12; c++) {
        float bv = sB[tx + 16 * c];
        #pragma unroll
        for (int r = 0; r < 4; r++) acc[r][c] = bv;
    }

    for (int kc = 0; kc < 4; kc++) {
        for (int i = tid; i < 64 * 32; i += 256) {
            int row = i >> 5, kk = i & 31;
            int v = b0 + row;
            sA[row][kk] = (v < 5000) ? tok_emb[v * 128 + kc * 32 + kk] : 0.0f;
        }
        for (int i = tid; i < 32 * 192; i += 256) {
            int k = i / 192, c = i % 192, d = c / 96, cc = c % 96;
            const float* gkp = d ? gk_bw : gk_fw;
            const float* ckp = d ? ck_bw : ck_fw;
            int row = kc * 32 + k;
            sW[k][c] = (cc < 64) ? gkp[row * 64 + cc] : ckp[row * 32 + (cc - 64)];
        }
        __syncthreads();
        #pragma unroll
        for (int k = 0; k < 32; k++) {
            float a[4];
            #pragma unroll
            for (int r = 0; r < 4; r++) a[r] = sA[ty * 4 + r][k];
            #pragma unroll
            for (int c = 0; c < 12; c++) {
                float bv = sW[k][tx + 16 * c];
                #pragma unroll
                for (int r = 0; r < 4; r++) acc[r][c] = fmaf(a[r], bv, acc[r][c]);
            }
        }
        __syncthreads();
    }

    #pragma unroll
    for (int r = 0; r < 4; r++) {
        int v = b0 + ty * 4 + r;
        if (v < 5000)
            #pragma unroll
            for (int c = 0; c < 12; c++)
                d_TW[(size_t)v * 192 + tx + 16 * c] = acc[r][c];
    }
}

// ---------------- K2: layer0 x-precompute, typemax (shfl) fused, f32x2 -----
__global__ void k_xw0(const int* __restrict__ tok_b, const int* __restrict__ tok_a,
                      const int* __restrict__ typ_b, const void* __restrict__ msk_b,
                      const int* __restrict__ typ_a, const void* __restrict__ msk_a,
                      const float* __restrict__ yemb,
                      const float* __restrict__ gkx_fw, const float* __restrict__ ckx_fw,
                      const float* __restrict__ gkx_bw, const float* __restrict__ ckx_bw)
{
    __shared__ float sA[64][33];
    __shared__ __align__(8) float sW[32][96];
    __shared__ int   sTok[64];
    int rt  = blockIdx.x;                // 0..2687
    int t   = rt >> 7;
    int b0  = (rt & 127) << 6;
    int tid = threadIdx.x;
    int tx = tid & 15, ty = tid >> 4;

    if (t == 10) {                       // hole: identical row for all b
        for (int dir = 0; dir < 2; dir++) {
            float* outp = d_XW0 + ((size_t)(dir * TT + t) * NB + b0) * 96;
            #pragma unroll
            for (int c = 0; c < 6; c++) {
                int col = tx + 16 * c;
                float v = d_HW[dir * 96 + col];
                #pragma unroll
                for (int r = 0; r < 4; r++) outp[(ty * 4 + r) * 96 + col] = v;
            }
        }
        return;
    }

    // ---- fused masked type-max: lane-parallel id/mask load + shfl ----
    {
        unsigned flags = d_maskFlags;
        int mode = ((flags & 1u) == 0u) ? 1 : (((flags & 2u) == 0u) ? 2 : 0);
        int wid = tid >> 5, lane = tid & 31;
        int pos = (t < 10) ? t : t - 11;
        const int*  typ = (t < 10) ? typ_b : typ_a;
        const void* msk = (t < 10) ? msk_b : msk_a;
        for (int rr = wid; rr < 64; rr += 8) {
            int bb = b0 + rr;
            int base = (bb * 10 + pos) * 10;
            int id0 = 0;
            float pen0 = -1000.0f;
            if (lane < 10) {
                id0 = typ[base + lane];
                bool valid;
                if (mode == 1)      valid = ((const int*)msk)[base + lane] != 0;
                else if (mode == 2) valid = ((const float*)msk)[base + lane] != 0.0f;
                else                valid = ((const unsigned char*)msk)[base + lane] != 0;
                pen0 = valid ? 0.0f : -1000.0f;
            }
            float m = -3.402823e38f;
            #pragma unroll
            for (int nt = 0; nt < 10; nt++) {
                int id  = __shfl_sync(0xffffffffu, id0,  nt);
                float p = __shfl_sync(0xffffffffu, pen0, nt);
                m = fmaxf(m, yemb[id * 32 + lane] + p);
            }
            sA[rr][lane] = m;
        }
    }
    if (tid < 64) {
        int bb = b0 + tid;
        sTok[tid] = (t < 10) ? tok_b[bb * 10 + t] : tok_a[bb * 10 + (t - 11)];
    }

    for (int dir = 0; dir < 2; dir++) {
        const float* gkx = dir ? gkx_bw : gkx_fw;
        const float* ckx = dir ? ckx_bw : ckx_fw;
        for (int i = tid; i < 32 * 64; i += 256) sW[i >> 6][i & 63]        = gkx[i];
        for (int i = tid; i < 32 * 32; i += 256) sW[i >> 5][64 + (i & 31)] = ckx[i];
        __syncthreads();

        u64t acc2[4][3];
        #pragma unroll
        for (int r = 0; r < 4; r++)
            #pragma unroll
            for (int c = 0; c < 3; c++) acc2[r][c] = pack2(0.0f, 0.0f);

        #pragma unroll
        for (int k = 0; k < 32; k++) {
            float a[4];
            u64t w2[3];
            #pragma unroll
            for (int r = 0; r < 4; r++) a[r] = sA[ty * 4 + r][k];
            #pragma unroll
            for (int c = 0; c < 3; c++)
                w2[c] = *(const u64t*)&sW[k][tx * 2 + 32 * c];
            #pragma unroll
            for (int r = 0; r < 4; r++) {
                u64t a2 = pack2(a[r], a[r]);
                #pragma unroll
                for (int c = 0; c < 3; c++) acc2[r][c] = fma2(a2, w2[c], acc2[r][c]);
            }
        }

        float* outp = d_XW0 + ((size_t)(dir * TT + t) * NB + b0) * 96;
        #pragma unroll
        for (int r = 0; r < 4; r++) {
            const float* tw = d_TW + (size_t)sTok[ty * 4 + r] * 192 + dir * 96;
            #pragma unroll
            for (int c = 0; c < 3; c++) {
                int col = tx * 2 + 32 * c;
                u64t o = add2(acc2[r][c], *(const u64t*)(tw + col));
                *(u64t*)(outp + (ty * 4 + r) * 96 + col) = o;
            }
        }
        __syncthreads();                 // before restaging sW for next dir
    }
}

// ---------------- K3: fused recurrence, 3 rows per warp --------------------
// 512 threads = 16 warps; warp = (dir, rowtriple); 24 batch rows per block.
// smem (floats):
//  G0R/G0U/C0, G1R/G1U/C1: k-paired rec weights [dir][k2][lane][2]  6 x 2048
//  B1:  layer1 bias [dir][96]                                       192
//  Y:   layer0 output, channel-major [24 rows][64 ch][22]           33792
//  H:   per-warp broadcast: hA,hB,hC,rhA,rhB,rhC @ 36 each [16][216] 3456
// Layer1 x-weights read via __ldg (L2/L1), not staged.
#define SM_G0R 0
#define SM_G0U 2048
#define SM_C0  4096
#define SM_G1R 6144
#define SM_G1U 8192
#define SM_C1  10240
#define SM_B1  12288
#define SM_Y   12480
#define SM_H   46272
#define SM_TOTF 49728
#define SM_BYTES (SM_TOTF * 4)

__global__ __launch_bounds__(512, 1)
void k_fused(const float* __restrict__ gk_fw0, const float* __restrict__ ck_fw0,
             const float* __restrict__ gk_bw0, const float* __restrict__ ck_bw0,
             const float* __restrict__ gk_fw1, const float* __restrict__ gb_fw1,
             const float* __restrict__ ck_fw1, const float* __restrict__ cb_fw1,
             const float* __restrict__ gk_bw1, const float* __restrict__ gb_bw1,
             const float* __restrict__ ck_bw1, const float* __restrict__ cb_bw1,
             float* __restrict__ out)
{
    extern __shared__ float sm[];
    int tid = threadIdx.x;

    // ---- stage rec weights once (k-paired layouts) ----
    for (int i = tid; i < 2048; i += 512) {
        int p = i & 1, ln = (i >> 1) & 31, k2 = (i >> 6) & 15, d = i >> 10;
        const float* gk0 = d ? gk_bw0 : gk_fw0;
        const float* ck0 = d ? ck_bw0 : ck_fw0;
        const float* gk1 = d ? gk_bw1 : gk_fw1;
        const float* ck1 = d ? ck_bw1 : ck_fw1;
        int r0 = 160 + 2 * k2 + p;       // layer0 h-part rows
        int r1 = 64 + 2 * k2 + p;        // layer1 h-part rows
        sm[SM_G0R + i] = gk0[r0 * 64 + ln];
        sm[SM_G0U + i] = gk0[r0 * 64 + 32 + ln];
        sm[SM_C0  + i] = ck0[r0 * 32 + ln];
        sm[SM_G1R + i] = gk1[r1 * 64 + ln];
        sm[SM_G1U + i] = gk1[r1 * 64 + 32 + ln];
        sm[SM_C1  + i] = ck1[r1 * 32 + ln];
    }
    if (tid < 192) {
        int d = tid / 96, c = tid % 96;
        sm[SM_B1 + tid] = (c < 64) ? (d ? gb_bw1 : gb_fw1)[c]
                                   : (d ? cb_bw1 : cb_fw1)[c - 64];
    }
    __syncthreads();

    int lane = tid & 31, wid = tid >> 5;
    int dir = wid >> 3, g = wid & 7;
    int rA = g * 3;
    int base = blockIdx.x * 24;
    if (base > NB - 24) base = NB - 24;  // last block overlaps (identical values)
    int bA = base + rA;
    float* yA = sm + SM_Y + (rA + 0) * 1408;   // [64 ch][22]
    float* yB = sm + SM_Y + (rA + 1) * 1408;
    float* yC = sm + SM_Y + (rA + 2) * 1408;
    float* hbuf = sm + SM_H + wid * 216;       // hA@0 hB@36 hC@72 rh@108/144/180
    const float* g0r = sm + SM_G0R + dir * 1024;
    const float* g0u = sm + SM_G0U + dir * 1024;
    const float* c0w = sm + SM_C0  + dir * 1024;

    // ---- layer0 recurrence, 3 rows interleaved; Y channel-major in smem ----
    {
        float hA = 0.0f, hB = 0.0f, hC = 0.0f;
        int t0 = dir ? 20 : 0;
        const float* xw = d_XW0 + ((size_t)(dir * TT + t0) * NB + bA) * 96;
        float nrA = xw[lane],       nuA = xw[32 + lane],  ncA = xw[64 + lane];
        float nrB = xw[96 + lane],  nuB = xw[128 + lane], ncB = xw[160 + lane];
        float nrC = xw[192 + lane], nuC = xw[224 + lane], ncC = xw[256 + lane];
        for (int s = 0; s < 21; s++) {
            int t = dir ? 20 - s : s;
            float xrA = nrA, xuA = nuA, xcA = ncA;
            float xrB = nrB, xuB = nuB, xcB = ncB;
            float xrC = nrC, xuC = nuC, xcC = ncC;
            if (s < 20) {
                int t2 = dir ? t - 1 : t + 1;
                const float* xn = d_XW0 + ((size_t)(dir * TT + t2) * NB + bA) * 96;
                nrA = xn[lane];       nuA = xn[32 + lane];  ncA = xn[64 + lane];
                nrB = xn[96 + lane];  nuB = xn[128 + lane]; ncB = xn[160 + lane];
                nrC = xn[192 + lane]; nuC = xn[224 + lane]; ncC = xn[256 + lane];
            }
            __syncwarp();
            hbuf[lane] = hA;
            hbuf[36 + lane] = hB;
            hbuf[72 + lane] = hC;
            __syncwarp();
            u64t arA = pack2(xrA, 0.0f), auA = pack2(xuA, 0.0f);
            u64t arB = pack2(xrB, 0.0f), auB = pack2(xuB, 0.0f);
            u64t arC = pack2(xrC, 0.0f), auC = pack2(xuC, 0.0f);
            #pragma unroll
            for (int k2 = 0; k2 < 16; k2++) {
                u64t hpA = *(const u64t*)(hbuf + 2 * k2);
                u64t hpB = *(const u64t*)(hbuf + 36 + 2 * k2);
                u64t hpC = *(const u64t*)(hbuf + 72 + 2 * k2);
                u64t wr = *(const u64t*)(g0r + (k2 * 32 + lane) * 2);
                u64t wu = *(const u64t*)(g0u + (k2 * 32 + lane) * 2);
                arA = fma2(wr, hpA, arA); arB = fma2(wr, hpB, arB); arC = fma2(wr, hpC, arC);
                auA = fma2(wu, hpA, auA); auB = fma2(wu, hpB, auB); auC = fma2(wu, hpC, auC);
            }
            float l0, l1;
            unpack2(arA, l0, l1); float rgA = sigf(l0 + l1);
            unpack2(auA, l0, l1); float ugA = sigf(l0 + l1);
            unpack2(arB, l0, l1); float rgB = sigf(l0 + l1);
            unpack2(auB, l0, l1); float ugB = sigf(l0 + l1);
            unpack2(arC, l0, l1); float rgC = sigf(l0 + l1);
            unpack2(auC, l0, l1); float ugC = sigf(l0 + l1);
            float rhA = rgA * hA, rhB = rgB * hB, rhC = rgC * hC;
            hbuf[108 + lane] = rhA;
            hbuf[144 + lane] = rhB;
            hbuf[180 + lane] = rhC;
            __syncwarp();
            u64t acA = pack2(xcA, 0.0f), acB = pack2(xcB, 0.0f), acC = pack2(xcC, 0.0f);
            #pragma unroll
            for (int k2 = 0; k2 < 16; k2++) {
                u64t rpA = *(const u64t*)(hbuf + 108 + 2 * k2);
                u64t rpB = *(const u64t*)(hbuf + 144 + 2 * k2);
                u64t rpC = *(const u64t*)(hbuf + 180 + 2 * k2);
                u64t wc = *(const u64t*)(c0w + (k2 * 32 + lane) * 2);
                acA = fma2(wc, rpA, acA); acB = fma2(wc, rpB, acB); acC = fma2(wc, rpC, acC);
            }
            unpack2(acA, l0, l1); float cA = tanhx(l0 + l1);
            unpack2(acB, l0, l1); float cB = tanhx(l0 + l1);
            unpack2(acC, l0, l1); float cC = tanhx(l0 + l1);
            hA = fmaf(ugA, hA - cA, cA);
            hB = fmaf(ugB, hB - cB, cB);
            hC = fmaf(ugC, hC - cC, cC);
            yA[(dir * 32 + lane) * 22 + t] = hA;
            yB[(dir * 32 + lane) * 22 + t] = hB;
            yC[(dir * 32 + lane) * 22 + t] = hC;
        }
    }
    __syncthreads();

    // ---- xw1 GEMV: t-paired f32x2 over channel-major Y; weights via LDG ----
    float accr_s[3][21], accu_s[3][21], accc_s[3][21];  // local (dyn-indexed)
    {
        const float* gk1 = dir ? gk_bw1 : gk_fw1;
        const float* ck1 = dir ? ck_bw1 : ck_fw1;
        float br = sm[SM_B1 + dir * 96 + lane];
        float bu = sm[SM_B1 + dir * 96 + 32 + lane];
        float bc = sm[SM_B1 + dir * 96 + 64 + lane];
        #pragma unroll
        for (int rr = 0; rr < 3; rr++) {
            const float* yrow = sm + SM_Y + (rA + rr) * 1408;
            u64t ar2[10], au2[10], ac2[10];
            float ar20 = br, au20 = bu, ac20 = bc;
            #pragma unroll
            for (int tp = 0; tp < 10; tp++) {
                ar2[tp] = pack2(br, br); au2[tp] = pack2(bu, bu); ac2[tp] = pack2(bc, bc);
            }
            for (int k = 0; k < 64; k++) {
                float wr = __ldg(gk1 + k * 64 + lane);
                float wu = __ldg(gk1 + k * 64 + 32 + lane);
                float wc = __ldg(ck1 + k * 32 + lane);
                u64t wr2 = pack2(wr, wr), wu2 = pack2(wu, wu), wc2 = pack2(wc, wc);
                const u64t* yk = (const u64t*)(yrow + k * 22);
                #pragma unroll
                for (int tp = 0; tp < 10; tp++) {
                    u64t yp = yk[tp];
                    ar2[tp] = fma2(wr2, yp, ar2[tp]);
                    au2[tp] = fma2(wu2, yp, au2[tp]);
                    ac2[tp] = fma2(wc2, yp, ac2[tp]);
                }
                float y20 = yrow[k * 22 + 20];
                ar20 = fmaf(wr, y20, ar20);
                au20 = fmaf(wu, y20, au20);
                ac20 = fmaf(wc, y20, ac20);
            }
            // unpack into step order: step s handles t = dir?20-s:s
            if (dir == 0) {
                #pragma unroll
                for (int tp = 0; tp < 10; tp++) {
                    unpack2(ar2[tp], accr_s[rr][2 * tp], accr_s[rr][2 * tp + 1]);
                    unpack2(au2[tp], accu_s[rr][2 * tp], accu_s[rr][2 * tp + 1]);
                    unpack2(ac2[tp], accc_s[rr][2 * tp], accc_s[rr][2 * tp + 1]);
                }
                accr_s[rr][20] = ar20; accu_s[rr][20] = au20; accc_s[rr][20] = ac20;
            } else {
                #pragma unroll
                for (int tp = 0; tp < 10; tp++) {
                    unpack2(ar2[tp], accr_s[rr][20 - 2 * tp], accr_s[rr][19 - 2 * tp]);
                    unpack2(au2[tp], accu_s[rr][20 - 2 * tp], accu_s[rr][19 - 2 * tp]);
                    unpack2(ac2[tp], accc_s[rr][20 - 2 * tp], accc_s[rr][19 - 2 * tp]);
                }
                accr_s[rr][0] = ar20; accu_s[rr][0] = au20; accc_s[rr][0] = ac20;
            }
        }
    }

    // ---- layer1 recurrence, 3 rows interleaved ----
    {
        const float* g1r = sm + SM_G1R + dir * 1024;
        const float* g1u = sm + SM_G1U + dir * 1024;
        const float* c1w = sm + SM_C1  + dir * 1024;
        float hA = 0.0f, hB = 0.0f, hC = 0.0f;
        for (int s = 0; s < 21; s++) {
            float xrA = accr_s[0][s], xuA = accu_s[0][s], xcA = accc_s[0][s];
            float xrB = accr_s[1][s], xuB = accu_s[1][s], xcB = accc_s[1][s];
            float xrC = accr_s[2][s], xuC = accu_s[2][s], xcC = accc_s[2][s];
            __syncwarp();
            hbuf[lane] = hA;
            hbuf[36 + lane] = hB;
            hbuf[72 + lane] = hC;
            __syncwarp();
            u64t arA = pack2(xrA, 0.0f), auA = pack2(xuA, 0.0f);
            u64t arB = pack2(xrB, 0.0f), auB = pack2(xuB, 0.0f);
            u64t arC = pack2(xrC, 0.0f), auC = pack2(xuC, 0.0f);
            #pragma unroll
            for (int k2 = 0; k2 < 16; k2++) {
                u64t hpA = *(const u64t*)(hbuf + 2 * k2);
                u64t hpB = *(const u64t*)(hbuf + 36 + 2 * k2);
                u64t hpC = *(const u64t*)(hbuf + 72 + 2 * k2);
                u64t wr = *(const u64t*)(g1r + (k2 * 32 + lane) * 2);
                u64t wu = *(const u64t*)(g1u + (k2 * 32 + lane) * 2);
                arA = fma2(wr, hpA, arA); arB = fma2(wr, hpB, arB); arC = fma2(wr, hpC, arC);
                auA = fma2(wu, hpA, auA); auB = fma2(wu, hpB, auB); auC = fma2(wu, hpC, auC);
            }
            float l0, l1;
            unpack2(arA, l0, l1); float rgA = sigf(l0 + l1);
            unpack2(auA, l0, l1); float ugA = sigf(l0 + l1);
            unpack2(arB, l0, l1); float rgB = sigf(l0 + l1);
            unpack2(auB, l0, l1); float ugB = sigf(l0 + l1);
            unpack2(arC, l0, l1); float rgC = sigf(l0 + l1);
            unpack2(auC, l0, l1); float ugC = sigf(l0 + l1);
            float rhA = rgA * hA, rhB = rgB * hB, rhC = rgC * hC;
            hbuf[108 + lane] = rhA;
            hbuf[144 + lane] = rhB;
            hbuf[180 + lane] = rhC;
            __syncwarp();
            u64t acA = pack2(xcA, 0.0f), acB = pack2(xcB, 0.0f), acC = pack2(xcC, 0.0f);
            #pragma unroll
            for (int k2 = 0; k2 < 16; k2++) {
                u64t rpA = *(const u64t*)(hbuf + 108 + 2 * k2);
                u64t rpB = *(const u64t*)(hbuf + 144 + 2 * k2);
                u64t rpC = *(const u64t*)(hbuf + 180 + 2 * k2);
                u64t wc = *(const u64t*)(c1w + (k2 * 32 + lane) * 2);
                acA = fma2(wc, rpA, acA); acB = fma2(wc, rpB, acB); acC = fma2(wc, rpC, acC);
            }
            unpack2(acA, l0, l1); float cA = tanhx(l0 + l1);
            unpack2(acB, l0, l1); float cB = tanhx(l0 + l1);
            unpack2(acC, l0, l1); float cC = tanhx(l0 + l1);
            hA = fmaf(ugA, hA - cA, cA);
            hB = fmaf(ugB, hB - cB, cB);
            hC = fmaf(ugC, hC - cC, cC);
            int t = dir ? 20 - s : s;
            out[((size_t)(bA + 0) * TT + t) * 64 + dir * 32 + lane] = hA;
            out[((size_t)(bA + 1) * TT + t) * 64 + dir * 32 + lane] = hB;
            out[((size_t)(bA + 2) * TT + t) * 64 + dir * 32 + lane] = hC;
        }
    }
}

// ---------------- launch ----------------------------------------------------
extern "C" void kernel_launch(void* const* d_in, const int* in_sizes, int n_in,
                              void* d_out, int out_size)
{
    const int*   tok_b = (const int*)d_in[0];
    const int*   typ_b = (const int*)d_in[1];
    const void*  msk_b = (const void*)d_in[2];
    const int*   tok_a = (const int*)d_in[3];
    const int*   typ_a = (const int*)d_in[4];
    const void*  msk_a = (const void*)d_in[5];
    const float* temb = (const float*)d_in[6];
    const float* yemb = (const float*)d_in[7];
    const float* hole = (const float*)d_in[8];
    const float* gk_fw0 = (const float*)d_in[9];
    const float* gb_fw0 = (const float*)d_in[10];
    const float* ck_fw0 = (const float*)d_in[11];
    const float* cb_fw0 = (const float*)d_in[12];
    const float* gk_bw0 = (const float*)d_in[13];
    const float* gb_bw0 = (const float*)d_in[14];
    const float* ck_bw0 = (const float*)d_in[15];
    const float* cb_bw0 = (const float*)d_in[16];
    const float* gk_fw1 = (const float*)d_in[17];
    const float* gb_fw1 = (const float*)d_in[18];
    const float* ck_fw1 = (const float*)d_in[19];
    const float* cb_fw1 = (const float*)d_in[20];
    const float* gk_bw1 = (const float*)d_in[21];
    const float* gb_bw1 = (const float*)d_in[22];
    const float* ck_bw1 = (const float*)d_in[23];
    const float* cb_bw1 = (const float*)d_in[24];
    float* out = (float*)d_out;

    cudaFuncSetAttribute(k_fused, cudaFuncAttributeMaxDynamicSharedMemorySize, SM_BYTES);

    // 0) detect mask dtype (uint8 vs int32 vs float32)
    k_reset<<<1, 1>>>();
    k_detect<<<148, 256>>>((const unsigned*)msk_b);

    // 1) token table (tiled GEMM) with hole row as block 79
    k_tables2<<<80, 256>>>(temb, hole,
                           gk_fw0, gb_fw0, ck_fw0, cb_fw0,
                           gk_bw0, gb_bw0, ck_bw0, cb_bw0);

    // 2) layer0 x-precompute, typemax fused (shfl), f32x2 GEMM, both dirs
    k_xw0<<<2688, 256>>>(tok_b, tok_a,
                         typ_b, msk_b, typ_a, msk_a, yemb,
                         gk_fw0 + 128 * 64, ck_fw0 + 128 * 32,
                         gk_bw0 + 128 * 64, ck_bw0 + 128 * 32);

    // 3) fused: layer0 rec -> xw1 GEMV -> layer1 rec, 3 rows per warp
    k_fused<<<342, 512, SM_BYTES>>>(gk_fw0, ck_fw0, gk_bw0, ck_bw0,
                                    gk_fw1, gb_fw1, ck_fw1, cb_fw1,
                                    gk_bw1, gb_bw1, ck_bw1, cb_bw1,
                                    out);
}